// round 13
// baseline (speedup 1.0000x reference)
#include <cuda_runtime.h>
#include <cstdint>

// All2AllDenseEmbedding (gpu_num=1) == row gather:
//   out[row][:] = table[idx[row]][:], row in [0, 4096*26*2), row = 128B.
//
// FINAL — converged at the platform floor. Evidence (R4-R12, 9 passing
// variants): the timed warm-replay regime is pinned at 10.7-11.0us across
// MLP 4-16, occupancy 31-73%, __ldg/__ldcg, plain/.cs/bulk stores,
// 128/256-bit widths, and the cp.async (no-register-landing) path. The
// bound is ~27MB DRAM output writes + L2-resident table reads + graph
// replay overhead; no instruction-path lever moves it.
//
// This is the best-measured family member: 256-thread blocks, 32 rows/warp,
// one coalesced index load per lane, shfl distribution, 8 independent
// float4 gathers per thread (MLP=8, each table row = exactly one 128B
// line), 8 coalesced float4 stores. 832 blocks, exact tiling, no tail,
// single launch, 32 regs, no smem. Cold-profiled kernel: 9.9us (best of
// all variants).

static constexpr int  EMB_DIM        = 32;
static constexpr long NROWS          = 4096L * 26L * 2L;   // 212992
static constexpr int  THREADS        = 256;
static constexpr int  VECS_PER_ROW   = EMB_DIM / 4;        // 8 float4 per row
static constexpr int  ROWS_PER_WARP  = 32;
static constexpr int  WARPS_PER_BLOCK= THREADS / 32;       // 8
static constexpr int  ROWS_PER_BLOCK = WARPS_PER_BLOCK * ROWS_PER_WARP;  // 256
static constexpr int  BLOCKS         = (int)(NROWS / ROWS_PER_BLOCK);    // 832, exact
static constexpr int  STEPS          = 8;                  // 4 rows per step

__global__ __launch_bounds__(THREADS)
void gather_rows_kernel(const void*   __restrict__ idx_raw,
                        const float4* __restrict__ table,
                        float4*       __restrict__ out)
{
    const int lane = threadIdx.x & 31;
    const int warp = threadIdx.x >> 5;

    // ---- per-warp dtype probe (int32 vs int64 indices): the high words of
    // the first 32 8-byte pairs are all zero iff the data is int64 (values
    // < 2^20, P[false int32 verdict] ~ 0). Same 256B for every warp ->
    // L1-hot after first touch per SM; no block barrier needed.
    unsigned int hiw = ((const unsigned int*)idx_raw)[2 * lane + 1];
    const bool is32 = __any_sync(0xffffffffu, hiw != 0);

    const long rowBase = ((long)blockIdx.x * WARPS_PER_BLOCK + warp) * ROWS_PER_WARP;

    // ---- one coalesced index load: lane L carries row rowBase+L ----
    long long myIdx;
    if (is32) myIdx = (long long)__ldg(((const int*)idx_raw) + rowBase + lane);
    else      myIdx = __ldg(((const long long*)idx_raw) + rowBase + lane);

    const int subrow = lane >> 3;   // 0..3: row within a 4-row step
    const int col    = lane & 7;    // float4 slot within row

    // ---- distribute indices: step s covers rows rowBase + s*4 .. +3 ----
    long r[STEPS];
#pragma unroll
    for (int s = 0; s < STEPS; s++)
        r[s] = (long)__shfl_sync(0xffffffffu, myIdx, s * 4 + subrow);

    // ---- 8 independent gathers (MLP=8): each row = exactly one 128B line ----
    float4 v[STEPS];
#pragma unroll
    for (int s = 0; s < STEPS; s++)
        v[s] = __ldg(table + r[s] * VECS_PER_ROW + col);

    // ---- 8 coalesced stores (512B contiguous per warp per step) ----
#pragma unroll
    for (int s = 0; s < STEPS; s++)
        out[(rowBase + s * 4 + subrow) * VECS_PER_ROW + col] = v[s];
}

extern "C" void kernel_launch(void* const* d_in, const int* in_sizes, int n_in,
                              void* d_out, int out_size)
{
    // Pick the index tensor by element count (212992 vs 32,000,000).
    const void*  idx;
    const float* table;
    if (in_sizes[0] == (int)NROWS) {
        idx   = d_in[0];
        table = (const float*)d_in[1];
    } else {
        idx   = d_in[1];
        table = (const float*)d_in[0];
    }

    gather_rows_kernel<<<BLOCKS, THREADS>>>(idx, (const float4*)table, (float4*)d_out);
}

// round 14
// speedup vs baseline: 1.0029x; 1.0029x over previous
#include <cuda_runtime.h>
#include <cstdint>

// All2AllDenseEmbedding (gpu_num=1) == row gather:
//   out[row][:] = table[idx[row]][:], row in [0, 4096*26*2), row = 128B.
//
// R4/R13 proven-best shape (256 thr, 32 rows/warp, MLP=8 float4 gathers,
// 832 blocks exact). Last untried lever: __stwt write-through stores —
// the output is write-once dead data; write-through avoids L2 write-
// allocate churn against the warm table and targets the DRAM write drain
// that bounds the warm-replay regime.

static constexpr int  EMB_DIM        = 32;
static constexpr long NROWS          = 4096L * 26L * 2L;   // 212992
static constexpr int  THREADS        = 256;
static constexpr int  VECS_PER_ROW   = EMB_DIM / 4;        // 8 float4 per row
static constexpr int  ROWS_PER_WARP  = 32;
static constexpr int  WARPS_PER_BLOCK= THREADS / 32;       // 8
static constexpr int  ROWS_PER_BLOCK = WARPS_PER_BLOCK * ROWS_PER_WARP;  // 256
static constexpr int  BLOCKS         = (int)(NROWS / ROWS_PER_BLOCK);    // 832, exact
static constexpr int  STEPS          = 8;                  // 4 rows per step

__global__ __launch_bounds__(THREADS)
void gather_rows_kernel(const void*   __restrict__ idx_raw,
                        const float4* __restrict__ table,
                        float4*       __restrict__ out)
{
    const int lane = threadIdx.x & 31;
    const int warp = threadIdx.x >> 5;

    // ---- per-warp dtype probe (int32 vs int64 indices): high words of the
    // first 32 8-byte pairs are all zero iff int64 (values < 2^20).
    unsigned int hiw = ((const unsigned int*)idx_raw)[2 * lane + 1];
    const bool is32 = __any_sync(0xffffffffu, hiw != 0);

    const long rowBase = ((long)blockIdx.x * WARPS_PER_BLOCK + warp) * ROWS_PER_WARP;

    // ---- one coalesced index load: lane L carries row rowBase+L ----
    long long myIdx;
    if (is32) myIdx = (long long)__ldg(((const int*)idx_raw) + rowBase + lane);
    else      myIdx = __ldg(((const long long*)idx_raw) + rowBase + lane);

    const int subrow = lane >> 3;   // 0..3: row within a 4-row step
    const int col    = lane & 7;    // float4 slot within row

    // ---- distribute indices: step s covers rows rowBase + s*4 .. +3 ----
    long r[STEPS];
#pragma unroll
    for (int s = 0; s < STEPS; s++)
        r[s] = (long)__shfl_sync(0xffffffffu, myIdx, s * 4 + subrow);

    // ---- 8 independent gathers (MLP=8): each row = exactly one 128B line ----
    float4 v[STEPS];
#pragma unroll
    for (int s = 0; s < STEPS; s++)
        v[s] = __ldg(table + r[s] * VECS_PER_ROW + col);

    // ---- 8 coalesced write-through stores (512B contiguous per warp/step) ----
#pragma unroll
    for (int s = 0; s < STEPS; s++)
        __stwt(out + (rowBase + s * 4 + subrow) * VECS_PER_ROW + col, v[s]);
}

extern "C" void kernel_launch(void* const* d_in, const int* in_sizes, int n_in,
                              void* d_out, int out_size)
{
    // Pick the index tensor by element count (212992 vs 32,000,000).
    const void*  idx;
    const float* table;
    if (in_sizes[0] == (int)NROWS) {
        idx   = d_in[0];
        table = (const float*)d_in[1];
    } else {
        idx   = d_in[1];
        table = (const float*)d_in[0];
    }

    gather_rows_kernel<<<BLOCKS, THREADS>>>(idx, (const float4*)table, (float4*)d_out);
}

// round 15
// speedup vs baseline: 1.0239x; 1.0209x over previous
#include <cuda_runtime.h>
#include <cstdint>

// All2AllDenseEmbedding (gpu_num=1) == row gather:
//   out[row][:] = table[idx[row]][:], row in [0, 4096*26*2), row = 128B.
//
// FINAL — converged at the platform floor. Evidence (R4-R14, 11 passing
// variants): the timed warm-replay regime is pinned at 10.7-11.0us across
// MLP 4-16, occupancy 31-73%, load policy (__ldg/__ldcg/cp.async), store
// policy (plain/.cs/.wt/bulk-async), width (128/256-bit), register vs smem
// landing, and 1-vs-2 launches. The bound: ~27MB DRAM output writes +
// L2-resident table reads + graph-replay fixed cost.
//
// Best-measured family member: 256-thread blocks, 32 rows/warp, one
// coalesced index load per lane, shfl distribution, 8 independent float4
// gathers per thread (MLP=8; each table row = exactly one 128B line),
// 8 coalesced float4 stores. 832 blocks, exact tiling, no tail, single
// launch, 32 regs, no smem.

static constexpr int  EMB_DIM        = 32;
static constexpr long NROWS          = 4096L * 26L * 2L;   // 212992
static constexpr int  THREADS        = 256;
static constexpr int  VECS_PER_ROW   = EMB_DIM / 4;        // 8 float4 per row
static constexpr int  ROWS_PER_WARP  = 32;
static constexpr int  WARPS_PER_BLOCK= THREADS / 32;       // 8
static constexpr int  ROWS_PER_BLOCK = WARPS_PER_BLOCK * ROWS_PER_WARP;  // 256
static constexpr int  BLOCKS         = (int)(NROWS / ROWS_PER_BLOCK);    // 832, exact
static constexpr int  STEPS          = 8;                  // 4 rows per step

__global__ __launch_bounds__(THREADS)
void gather_rows_kernel(const void*   __restrict__ idx_raw,
                        const float4* __restrict__ table,
                        float4*       __restrict__ out)
{
    const int lane = threadIdx.x & 31;
    const int warp = threadIdx.x >> 5;

    // ---- per-warp dtype probe (int32 vs int64 indices): the high words of
    // the first 32 8-byte pairs are all zero iff the data is int64 (values
    // < 2^20). Same 256B for every warp -> L1-hot after first touch per SM;
    // no block barrier needed.
    unsigned int hiw = ((const unsigned int*)idx_raw)[2 * lane + 1];
    const bool is32 = __any_sync(0xffffffffu, hiw != 0);

    const long rowBase = ((long)blockIdx.x * WARPS_PER_BLOCK + warp) * ROWS_PER_WARP;

    // ---- one coalesced index load: lane L carries row rowBase+L ----
    long long myIdx;
    if (is32) myIdx = (long long)__ldg(((const int*)idx_raw) + rowBase + lane);
    else      myIdx = __ldg(((const long long*)idx_raw) + rowBase + lane);

    const int subrow = lane >> 3;   // 0..3: row within a 4-row step
    const int col    = lane & 7;    // float4 slot within row

    // ---- distribute indices: step s covers rows rowBase + s*4 .. +3 ----
    long r[STEPS];
#pragma unroll
    for (int s = 0; s < STEPS; s++)
        r[s] = (long)__shfl_sync(0xffffffffu, myIdx, s * 4 + subrow);

    // ---- 8 independent gathers (MLP=8): each row = exactly one 128B line ----
    float4 v[STEPS];
#pragma unroll
    for (int s = 0; s < STEPS; s++)
        v[s] = __ldg(table + r[s] * VECS_PER_ROW + col);

    // ---- 8 coalesced stores (512B contiguous per warp per step) ----
#pragma unroll
    for (int s = 0; s < STEPS; s++)
        out[(rowBase + s * 4 + subrow) * VECS_PER_ROW + col] = v[s];
}

extern "C" void kernel_launch(void* const* d_in, const int* in_sizes, int n_in,
                              void* d_out, int out_size)
{
    // Pick the index tensor by element count (212992 vs 32,000,000).
    const void*  idx;
    const float* table;
    if (in_sizes[0] == (int)NROWS) {
        idx   = d_in[0];
        table = (const float*)d_in[1];
    } else {
        idx   = d_in[1];
        table = (const float*)d_in[0];
    }

    gather_rows_kernel<<<BLOCKS, THREADS>>>(idx, (const float4*)table, (float4*)d_out);
}